// round 2
// baseline (speedup 1.0000x reference)
#include <cuda_runtime.h>
#include <cstdint>

// PointPillars scatter, inverted as index-map + gather.
// B=4, C=64, H=512, W=512, P=409600 (P read from in_sizes for safety).
#define B_ 4
#define C_ 64
#define H_ 512
#define W_ 512
#define HW_ (H_ * W_)        // 262144 = 2^18
#define BHW_ (B_ * HW_)      // 1048576

// 4 MB scratch: last-writer pillar index per BEV cell (-1 = empty).
__device__ int g_map[BHW_];

// ---------------------------------------------------------------------------
// Kernel 1: init map to -1 (vectorized int4).
__global__ void k_init_map() {
    int i = blockIdx.x * blockDim.x + threadIdx.x;
    if (i < BHW_ / 4) {
        reinterpret_cast<int4*>(g_map)[i] = make_int4(-1, -1, -1, -1);
    }
}

// ---------------------------------------------------------------------------
// Kernel 2: scatter pillar indices. atomicMax => highest pillar index wins,
// which equals sequential last-write-wins of the reference.
__global__ void k_scatter_idx(const int* __restrict__ coords, int P) {
    int p = blockIdx.x * blockDim.x + threadIdx.x;
    if (p >= P) return;
    int4 c = reinterpret_cast<const int4*>(coords)[p];  // [b, z, y, x]
    int b = c.x, y = c.z, x = c.w;
    if ((unsigned)y < H_ && (unsigned)x < W_) {
        atomicMax(&g_map[(b * H_ + y) * W_ + x], p);
    }
}

// ---------------------------------------------------------------------------
// Kernel 3: gather. One thread per BEV cell owns all 64 channels.
// Feature row read: 16x float4 = 256B contiguous per occupied cell.
// Output writes: stride HW_ across channels, coalesced across the warp in w.
__global__ void __launch_bounds__(256) k_gather(const float* __restrict__ feat,
                                                float* __restrict__ out) {
    int s = blockIdx.x * blockDim.x + threadIdx.x;   // 0 .. BHW_-1
    int b  = s >> 18;            // / HW_
    int sp = s & (HW_ - 1);      // within-batch spatial index

    int pid = g_map[s];

    float4 v[16];
    if (pid >= 0) {
        const float4* fp = reinterpret_cast<const float4*>(feat + (size_t)pid * C_);
#pragma unroll
        for (int i = 0; i < 16; i++) v[i] = fp[i];
    } else {
#pragma unroll
        for (int i = 0; i < 16; i++) v[i] = make_float4(0.f, 0.f, 0.f, 0.f);
    }

    float* op = out + (size_t)b * (C_ * HW_) + sp;
#pragma unroll
    for (int i = 0; i < 16; i++) {
        op[(size_t)(4 * i + 0) * HW_] = v[i].x;
        op[(size_t)(4 * i + 1) * HW_] = v[i].y;
        op[(size_t)(4 * i + 2) * HW_] = v[i].z;
        op[(size_t)(4 * i + 3) * HW_] = v[i].w;
    }
}

// ---------------------------------------------------------------------------
extern "C" void kernel_launch(void* const* d_in, const int* in_sizes, int n_in,
                              void* d_out, int out_size) {
    const float* feat   = (const float*)d_in[0];   // [P, C] float32
    const int*   coords = (const int*)d_in[1];     // [P, 4] int32
    int P = in_sizes[1] / 4;

    k_init_map<<<(BHW_ / 4 + 255) / 256, 256>>>();
    k_scatter_idx<<<(P + 255) / 256, 256>>>(coords, P);
    k_gather<<<BHW_ / 256, 256>>>(feat, (float*)d_out);
}

// round 3
// speedup vs baseline: 1.0218x; 1.0218x over previous
#include <cuda_runtime.h>
#include <cstdint>

// PointPillars scatter, inverted as index-map + gather.
// B=4, C=64, H=512, W=512, P=409600 (P read from in_sizes for safety).
#define B_ 4
#define C_ 64
#define H_ 512
#define W_ 512
#define HW_ (H_ * W_)        // 262144 = 2^18
#define BHW_ (B_ * HW_)      // 1048576

// 4 MB scratch: last-writer pillar index per BEV cell (-1 = empty).
__device__ int g_map[BHW_];

// ---------------------------------------------------------------------------
// Kernel 1: init map to -1 (vectorized int4).
__global__ void k_init_map() {
    int i = blockIdx.x * blockDim.x + threadIdx.x;
    if (i < BHW_ / 4) {
        reinterpret_cast<int4*>(g_map)[i] = make_int4(-1, -1, -1, -1);
    }
}

// ---------------------------------------------------------------------------
// Kernel 2: scatter pillar indices. atomicMax => highest pillar index wins,
// which equals sequential last-write-wins of the reference.
__global__ void k_scatter_idx(const int* __restrict__ coords, int P) {
    int p = blockIdx.x * blockDim.x + threadIdx.x;
    if (p >= P) return;
    int4 c = reinterpret_cast<const int4*>(coords)[p];  // [b, z, y, x]
    int b = c.x, y = c.z, x = c.w;
    if ((unsigned)y < H_ && (unsigned)x < W_) {
        atomicMax(&g_map[(b * H_ + y) * W_ + x], p);
    }
}

// ---------------------------------------------------------------------------
// Kernel 3: gather. One thread per BEV cell owns all 64 channels.
// Feature row read: 16x float4 = 256B contiguous per occupied cell.
// Output writes: stride HW_ across channels, coalesced across the warp in w.
__global__ void __launch_bounds__(256) k_gather(const float* __restrict__ feat,
                                                float* __restrict__ out) {
    int s = blockIdx.x * blockDim.x + threadIdx.x;   // 0 .. BHW_-1
    int b  = s >> 18;            // / HW_
    int sp = s & (HW_ - 1);      // within-batch spatial index

    int pid = g_map[s];

    float4 v[16];
    if (pid >= 0) {
        const float4* fp = reinterpret_cast<const float4*>(feat + (size_t)pid * C_);
#pragma unroll
        for (int i = 0; i < 16; i++) v[i] = fp[i];
    } else {
#pragma unroll
        for (int i = 0; i < 16; i++) v[i] = make_float4(0.f, 0.f, 0.f, 0.f);
    }

    float* op = out + (size_t)b * (C_ * HW_) + sp;
#pragma unroll
    for (int i = 0; i < 16; i++) {
        op[(size_t)(4 * i + 0) * HW_] = v[i].x;
        op[(size_t)(4 * i + 1) * HW_] = v[i].y;
        op[(size_t)(4 * i + 2) * HW_] = v[i].z;
        op[(size_t)(4 * i + 3) * HW_] = v[i].w;
    }
}

// ---------------------------------------------------------------------------
extern "C" void kernel_launch(void* const* d_in, const int* in_sizes, int n_in,
                              void* d_out, int out_size) {
    const float* feat   = (const float*)d_in[0];   // [P, C] float32
    const int*   coords = (const int*)d_in[1];     // [P, 4] int32
    int P = in_sizes[1] / 4;

    k_init_map<<<(BHW_ / 4 + 255) / 256, 256>>>();
    k_scatter_idx<<<(P + 255) / 256, 256>>>(coords, P);
    k_gather<<<BHW_ / 256, 256>>>(feat, (float*)d_out);
}